// round 16
// baseline (speedup 1.0000x reference)
#include <cuda_runtime.h>
#include <cuda_bf16.h>
#include <math.h>
#include <stdint.h>

#define NNODES 5461
#define NINT 1365
#define LEAF_START 1365
#define NLEAF 4096
#define DIM 512
#define KPS 1024          // stored split rows: A=[hi|lo], B=[Wh|Wl]
#define BKC 64
#define NIT 24            // logical K' = 1536 = 24 chunks of 64

// ---------------- scratch ----------------
__device__ __align__(16) __nv_bfloat16 g_xsplit[(size_t)NNODES * KPS];
__device__ __align__(16) __nv_bfloat16 g_hsplit[(size_t)NNODES * KPS];
__device__ __align__(16) __nv_bfloat16 g_hsumsplit[1024 * KPS];
__device__ __align__(16) __nv_bfloat16 g_Wmod[2][2048 * KPS];
__device__ __align__(16) __nv_bfloat16 g_Wiouh_m[2][1536 * KPS];
__device__ __align__(16) __nv_bfloat16 g_Wfh_m[2][512 * KPS];
__device__ float g_bmod[2][2048];
__device__ float g_pre[(size_t)NNODES * 2048];
__device__ float g_hsiou[1024 * 1536];
__device__ float g_fh[4096 * 512];
__device__ float g_c[NNODES * DIM];
__device__ int   g_sel[NNODES];
__device__ int   g_gcnt[4];
__device__ int   g_gidx[4][NNODES];
__device__ int   g_lcnt[12];
__device__ int   g_lidx_v[NINT];
__device__ int   g_lidx_l[NINT];

// fast activations (MUFU-only; ~1e-7 rel err vs 1e-3 tolerance)
__device__ __forceinline__ float sigmf(float x) { return 1.0f / (1.0f + __expf(-x)); }
__device__ __forceinline__ float tanhfast(float x) {
    return 2.0f / (1.0f + __expf(-2.0f * x)) - 1.0f;
}

// ---------------- PTX helpers ----------------
__device__ __forceinline__ uint32_t smem_u32(const void* p) {
    uint32_t a;
    asm("{ .reg .u64 t; cvta.to.shared.u64 t, %1; cvt.u32.u64 %0, t; }" : "=r"(a) : "l"(p));
    return a;
}
__device__ __forceinline__ void cpasync16(uint32_t dst, const void* src, int srcsize) {
    asm volatile("cp.async.cg.shared.global [%0], [%1], 16, %2;"
                 :: "r"(dst), "l"(src), "r"(srcsize) : "memory");
}
#define CP_COMMIT() asm volatile("cp.async.commit_group;" ::: "memory")
#define CP_WAIT1()  asm volatile("cp.async.wait_group 1;" ::: "memory")
#define CP_WAIT0()  asm volatile("cp.async.wait_group 0;" ::: "memory")

#define LDSM4(r, addr) \
    asm volatile("ldmatrix.sync.aligned.m8n8.x4.shared.b16 {%0,%1,%2,%3}, [%4];" \
                 : "=r"((r)[0]), "=r"((r)[1]), "=r"((r)[2]), "=r"((r)[3]) : "r"(addr))

#define MMA16816(d, a, b0_, b1_) \
    asm volatile("mma.sync.aligned.m16n8k16.row.col.f32.bf16.bf16.f32 " \
                 "{%0,%1,%2,%3}, {%4,%5,%6,%7}, {%8,%9}, {%0,%1,%2,%3};" \
                 : "+f"((d)[0]), "+f"((d)[1]), "+f"((d)[2]), "+f"((d)[3]) \
                 : "r"((a)[0]), "r"((a)[1]), "r"((a)[2]), "r"((a)[3]), "r"(b0_), "r"(b1_))

__device__ __forceinline__ uint32_t sw128(uint32_t off) {
    return off ^ ((off >> 3) & 0x70);
}
__device__ __forceinline__ void bsplit(float v, __nv_bfloat16& h, __nv_bfloat16& l) {
    h = __float2bfloat16(v);
    l = __float2bfloat16(v - __bfloat162float(h));
}

// ---------------- GEMM descriptors ----------------
struct GDesc {
    const __nv_bfloat16* A;
    const __nv_bfloat16* B;
    const float* bias;
    float* C;
    const int* cnt;
    const int* idx;
    int child4, sub, csub, ldc, Nc;
};
struct GDesc4 { GDesc d[4]; };

// ---------------- gemm_big: BM=128 BN=128, 2 CTAs/SM ----------------
#define TILE_BYTES_BIG 16384
#define SMEM_BIG (4 * TILE_BYTES_BIG)

__global__ void __launch_bounds__(256, 2) gemm_big(GDesc4 dd)
{
    const GDesc ds = dd.d[blockIdx.z];
    const int Nc = ds.Nc;
    const int col0 = blockIdx.x * 128;
    if (col0 >= Nc) return;
    const int nlist = *ds.cnt;
    const int Mrows = ds.child4 ? 4 * nlist : nlist;
    const int row0 = blockIdx.y * 128;
    if (row0 >= Mrows) return;

    extern __shared__ char smem[];
    const uint32_t sb = smem_u32(smem);
    const int tid  = threadIdx.x;
    const int wid  = tid >> 5;
    const int lane = tid & 31;
    const int wm   = wid & 3;
    const int wn   = wid >> 2;

    const int lrow = tid >> 1;
    const int lch0 = (tid & 1) * 4;
    const int g = row0 + lrow;
    int nodeA = 0, a_sz = 0;
    if (g < Mrows) {
        nodeA = ds.child4 ? (4 * ds.idx[g >> 2] + 1 + (g & 3)) : (ds.idx[g] - ds.sub);
        a_sz = 16;
    }
    const __nv_bfloat16* gA = ds.A + (size_t)nodeA * KPS + lch0 * 8;
    const __nv_bfloat16* gB = ds.B + (size_t)(col0 + lrow) * KPS + lch0 * 8;
    uint32_t sA[4], sB[4];
#pragma unroll
    for (int i = 0; i < 4; i++) {
        uint32_t off = sw128((uint32_t)(lrow * 128 + (lch0 + i) * 16));
        sA[i] = sb + off;
        sB[i] = sb + 2 * TILE_BYTES_BIG + off;
    }

    uint32_t rawA[2], rawB[4];
#pragma unroll
    for (int mi = 0; mi < 2; mi++)
        rawA[mi] = (uint32_t)((wm * 32 + mi * 16 + (lane & 15)) * 128 + ((lane >> 4) << 4));
#pragma unroll
    for (int ni = 0; ni < 4; ni++)
        rawB[ni] = (uint32_t)((wn * 64 + ni * 16 + (lane & 7) + ((lane >> 4) << 3)) * 128
                              + (((lane >> 3) & 1) << 4));

    float acc[2][8][4];
#pragma unroll
    for (int mi = 0; mi < 2; mi++)
#pragma unroll
        for (int nj = 0; nj < 8; nj++)
#pragma unroll
            for (int q = 0; q < 4; q++) acc[mi][nj][q] = 0.f;

    auto loadc = [&](int c, uint32_t bsel) {
        int cA = (c < 16) ? c : c - 16;
        int cB = (c < 8)  ? c : c - 8;
        const __nv_bfloat16* pa = gA + cA * BKC;
        const __nv_bfloat16* pb = gB + cB * BKC;
#pragma unroll
        for (int i = 0; i < 4; i++) {
            cpasync16(sA[i] + bsel, pa + i * 8, a_sz);
            cpasync16(sB[i] + bsel, pb + i * 8, 16);
        }
    };

    loadc(0, 0);
    CP_COMMIT();

    for (int c = 0; c < NIT; c++) {
        if (c + 1 < NIT) {
            loadc(c + 1, ((c + 1) & 1) * TILE_BYTES_BIG);
            CP_COMMIT();
            CP_WAIT1();
        } else {
            CP_WAIT0();
        }
        __syncthreads();

        const uint32_t abase = sb + (c & 1) * TILE_BYTES_BIG;
        const uint32_t bbase = sb + 2 * TILE_BYTES_BIG + (c & 1) * TILE_BYTES_BIG;
#pragma unroll
        for (int kb = 0; kb < 4; kb++) {
            const uint32_t kby = (uint32_t)(kb * 32);
            uint32_t a0[4], a1[4];
            LDSM4(a0, abase + sw128(rawA[0] + kby));
            LDSM4(a1, abase + sw128(rawA[1] + kby));
#pragma unroll
            for (int ni = 0; ni < 4; ni++) {
                uint32_t bt[4];
                LDSM4(bt, bbase + sw128(rawB[ni] + kby));
                MMA16816(acc[0][2 * ni],     a0, bt[0], bt[1]);
                MMA16816(acc[0][2 * ni + 1], a0, bt[2], bt[3]);
                MMA16816(acc[1][2 * ni],     a1, bt[0], bt[1]);
                MMA16816(acc[1][2 * ni + 1], a1, bt[2], bt[3]);
            }
        }
        __syncthreads();
    }

#pragma unroll
    for (int mi = 0; mi < 2; mi++) {
        int rbase = row0 + wm * 32 + mi * 16 + (lane >> 2);
#pragma unroll
        for (int half = 0; half < 2; half++) {
            int r = rbase + half * 8;
            if (r >= Mrows) continue;
            int node = ds.child4 ? (4 * ds.idx[r >> 2] + 1 + (r & 3)) : (ds.idx[r] - ds.sub);
            float* Crow = ds.C + (size_t)(node - ds.csub) * ds.ldc;
#pragma unroll
            for (int nj = 0; nj < 8; nj++) {
                int col = col0 + wn * 64 + nj * 8 + (lane & 3) * 2;
                float b0 = 0.f, b1 = 0.f;
                if (ds.bias) { b0 = ds.bias[col]; b1 = ds.bias[col + 1]; }
                float2 v = make_float2(acc[mi][nj][2 * half] + b0, acc[mi][nj][2 * half + 1] + b1);
                *(float2*)(Crow + col) = v;
            }
        }
    }
}

// ---------------- gemm_lvl: BM=128 BN=64, 3 CTAs/SM ----------------
#define A_TILE_BYTES 16384
#define B_TILE_BYTES 8192
#define SMEM_LVL (2 * A_TILE_BYTES + 2 * B_TILE_BYTES)   // 48 KB

__global__ void __launch_bounds__(256, 3) gemm_lvl(GDesc4 dd)
{
    const GDesc ds = dd.d[blockIdx.z];
    const int Nc = ds.Nc;
    const int col0 = blockIdx.x * 64;
    if (col0 >= Nc) return;
    const int nlist = *ds.cnt;
    const int Mrows = ds.child4 ? 4 * nlist : nlist;
    const int row0 = blockIdx.y * 128;
    if (row0 >= Mrows) return;

    extern __shared__ char smem[];
    const uint32_t sb = smem_u32(smem);
    const int tid  = threadIdx.x;
    const int wid  = tid >> 5;
    const int lane = tid & 31;
    const int wm   = wid & 3;
    const int wn   = wid >> 2;

    const int lrow = tid >> 1;
    const int lch0 = (tid & 1) * 4;
    const int g = row0 + lrow;
    int nodeA = 0, a_sz = 0;
    if (g < Mrows) {
        nodeA = ds.child4 ? (4 * ds.idx[g >> 2] + 1 + (g & 3)) : (ds.idx[g] - ds.sub);
        a_sz = 16;
    }
    const __nv_bfloat16* gA = ds.A + (size_t)nodeA * KPS + lch0 * 8;
    uint32_t sA[4];
#pragma unroll
    for (int i = 0; i < 4; i++)
        sA[i] = sb + sw128((uint32_t)(lrow * 128 + (lch0 + i) * 16));

    const int browB = tid >> 2;
    const int bch0  = (tid & 3) * 2;
    const __nv_bfloat16* gB = ds.B + (size_t)(col0 + browB) * KPS + bch0 * 8;
    uint32_t sB[2];
#pragma unroll
    for (int i = 0; i < 2; i++)
        sB[i] = sb + 2 * A_TILE_BYTES + sw128((uint32_t)(browB * 128 + (bch0 + i) * 16));

    uint32_t rawA[2], rawB[2];
#pragma unroll
    for (int mi = 0; mi < 2; mi++)
        rawA[mi] = (uint32_t)((wm * 32 + mi * 16 + (lane & 15)) * 128 + ((lane >> 4) << 4));
#pragma unroll
    for (int ni = 0; ni < 2; ni++)
        rawB[ni] = (uint32_t)((wn * 32 + ni * 16 + (lane & 7) + ((lane >> 4) << 3)) * 128
                              + (((lane >> 3) & 1) << 4));

    float acc[2][4][4];
#pragma unroll
    for (int mi = 0; mi < 2; mi++)
#pragma unroll
        for (int nj = 0; nj < 4; nj++)
#pragma unroll
            for (int q = 0; q < 4; q++) acc[mi][nj][q] = 0.f;

    auto loadc = [&](int c, int buf) {
        int cA = (c < 16) ? c : c - 16;
        int cB = (c < 8)  ? c : c - 8;
        const __nv_bfloat16* pa = gA + cA * BKC;
        const __nv_bfloat16* pb = gB + cB * BKC;
        uint32_t aoff = (uint32_t)buf * A_TILE_BYTES;
        uint32_t boff = (uint32_t)buf * B_TILE_BYTES;
#pragma unroll
        for (int i = 0; i < 4; i++) cpasync16(sA[i] + aoff, pa + i * 8, a_sz);
#pragma unroll
        for (int i = 0; i < 2; i++) cpasync16(sB[i] + boff, pb + i * 8, 16);
    };

    loadc(0, 0);
    CP_COMMIT();

    for (int c = 0; c < NIT; c++) {
        if (c + 1 < NIT) {
            loadc(c + 1, (c + 1) & 1);
            CP_COMMIT();
            CP_WAIT1();
        } else {
            CP_WAIT0();
        }
        __syncthreads();

        const uint32_t abase = sb + (c & 1) * A_TILE_BYTES;
        const uint32_t bbase = sb + 2 * A_TILE_BYTES + (c & 1) * B_TILE_BYTES;
#pragma unroll
        for (int kb = 0; kb < 4; kb++) {
            const uint32_t kby = (uint32_t)(kb * 32);
            uint32_t a0[4], a1[4];
            LDSM4(a0, abase + sw128(rawA[0] + kby));
            LDSM4(a1, abase + sw128(rawA[1] + kby));
#pragma unroll
            for (int ni = 0; ni < 2; ni++) {
                uint32_t bt[4];
                LDSM4(bt, bbase + sw128(rawB[ni] + kby));
                MMA16816(acc[0][2 * ni],     a0, bt[0], bt[1]);
                MMA16816(acc[0][2 * ni + 1], a0, bt[2], bt[3]);
                MMA16816(acc[1][2 * ni],     a1, bt[0], bt[1]);
                MMA16816(acc[1][2 * ni + 1], a1, bt[2], bt[3]);
            }
        }
        __syncthreads();
    }

#pragma unroll
    for (int mi = 0; mi < 2; mi++) {
        int rbase = row0 + wm * 32 + mi * 16 + (lane >> 2);
#pragma unroll
        for (int half = 0; half < 2; half++) {
            int r = rbase + half * 8;
            if (r >= Mrows) continue;
            int node = ds.child4 ? (4 * ds.idx[r >> 2] + 1 + (r & 3)) : (ds.idx[r] - ds.sub);
            float* Crow = ds.C + (size_t)(node - ds.csub) * ds.ldc;
#pragma unroll
            for (int nj = 0; nj < 4; nj++) {
                int col = col0 + wn * 32 + nj * 8 + (lane & 3) * 2;
                float b0 = 0.f, b1 = 0.f;
                if (ds.bias) { b0 = ds.bias[col]; b1 = ds.bias[col + 1]; }
                float2 v = make_float2(acc[mi][nj][2 * half] + b0, acc[mi][nj][2 * half + 1] + b1);
                *(float2*)(Crow + col) = v;
            }
        }
    }
}

// ---------------- fused preprocessing: pack weights (3 sets) + split x ----------------
#define R0 (2 * 2048 * 64)
#define R1 (2 * 1536 * 64)
#define R2 (2 * 512 * 64)
#define R3 (NNODES * 64)
#define PACK_TOTAL (R0 + R1 + R2 + R3)

__global__ void pack_all(const float* __restrict__ x,
                         const float* __restrict__ Wi_v, const float* __restrict__ Wi_l,
                         const float* __restrict__ Wf_v, const float* __restrict__ Wf_l,
                         const float* __restrict__ Wh_v, const float* __restrict__ Wh_l,
                         const float* __restrict__ Wfh_v, const float* __restrict__ Wfh_l,
                         const float* __restrict__ bi_v, const float* __restrict__ bi_l,
                         const float* __restrict__ bf_v, const float* __restrict__ bf_l)
{
    int idx = blockIdx.x * blockDim.x + threadIdx.x;
    if (idx >= PACK_TOTAL) return;

    if (idx < R0) {
        int m  = idx >> 17;
        int rem = idx & 131071;
        int kb = rem >> 11;
        int n  = rem & 2047;
        const float* W; int col, ld;
        if (n < 1536) { W = m ? Wi_l : Wi_v; col = n;        ld = 1536; }
        else          { W = m ? Wf_l : Wf_v; col = n - 1536; ld = 512;  }
        __nv_bfloat16 hi8[8], lo8[8];
#pragma unroll
        for (int j = 0; j < 8; j++) bsplit(W[(size_t)(kb * 8 + j) * ld + col], hi8[j], lo8[j]);
        __nv_bfloat16* dst = g_Wmod[m];
        size_t b = (size_t)n * KPS + kb * 8;
        *(uint4*)&dst[b]       = *(uint4*)hi8;
        *(uint4*)&dst[b + 512] = *(uint4*)lo8;
        if (kb == 0) {
            float bv;
            if (n < 1536) bv = m ? bi_l[n] : bi_v[n];
            else          bv = m ? bf_l[n - 1536] : bf_v[n - 1536];
            g_bmod[m][n] = bv;
        }
        return;
    }
    idx -= R0;
    if (idx < R1) {
        const int rows = 1536;
        int m  = idx / (rows * 64);
        int rem = idx - m * rows * 64;
        int kb = rem / rows;
        int n  = rem - kb * rows;
        const float* W = m ? Wh_l : Wh_v;
        __nv_bfloat16 hi8[8], lo8[8];
#pragma unroll
        for (int j = 0; j < 8; j++) bsplit(W[(size_t)(kb * 8 + j) * rows + n], hi8[j], lo8[j]);
        __nv_bfloat16* dst = &g_Wiouh_m[0][0];
        size_t b = (size_t)m * rows * KPS + (size_t)n * KPS + kb * 8;
        *(uint4*)&dst[b]       = *(uint4*)hi8;
        *(uint4*)&dst[b + 512] = *(uint4*)lo8;
        return;
    }
    idx -= R1;
    if (idx < R2) {
        const int rows = 512;
        int m  = idx / (rows * 64);
        int rem = idx - m * rows * 64;
        int kb = rem / rows;
        int n  = rem - kb * rows;
        const float* W = m ? Wfh_l : Wfh_v;
        __nv_bfloat16 hi8[8], lo8[8];
#pragma unroll
        for (int j = 0; j < 8; j++) bsplit(W[(size_t)(kb * 8 + j) * rows + n], hi8[j], lo8[j]);
        __nv_bfloat16* dst = &g_Wfh_m[0][0];
        size_t b = (size_t)m * rows * KPS + (size_t)n * KPS + kb * 8;
        *(uint4*)&dst[b]       = *(uint4*)hi8;
        *(uint4*)&dst[b + 512] = *(uint4*)lo8;
        return;
    }
    idx -= R2;
    {
        int n = idx >> 6, kb = idx & 63;
        __nv_bfloat16 hi8[8], lo8[8];
        const float* p = x + (size_t)n * DIM + kb * 8;
#pragma unroll
        for (int j = 0; j < 8; j++) bsplit(p[j], hi8[j], lo8[j]);
        size_t b = (size_t)n * KPS + kb * 8;
        *(uint4*)&g_xsplit[b]       = *(uint4*)hi8;
        *(uint4*)&g_xsplit[b + 512] = *(uint4*)lo8;
    }
}

// ---------------- zero counters ----------------
__global__ void zero_cnt()
{
    int t = threadIdx.x;
    if (t < 4)  g_gcnt[t] = 0;
    if (t < 12) g_lcnt[t] = 0;
}

// ---------------- selection + grouping (fused) ----------------
__global__ void sel_group(const float* __restrict__ x,
                          const float* __restrict__ Wt,
                          const float* __restrict__ bt)
{
    int n = blockIdx.x * (blockDim.x >> 5) + (threadIdx.x >> 5);
    int lane = threadIdx.x & 31;
    if (n >= NNODES) return;
    float s0 = 0.f, s1 = 0.f;
    const float* xr = x + (size_t)n * DIM;
#pragma unroll 4
    for (int k = lane; k < DIM; k += 32) {
        float xv = xr[k];
        s0 = fmaf(xv, Wt[k * 2 + 0], s0);
        s1 = fmaf(xv, Wt[k * 2 + 1], s1);
    }
#pragma unroll
    for (int o = 16; o > 0; o >>= 1) {
        s0 += __shfl_xor_sync(0xFFFFFFFFu, s0, o);
        s1 += __shfl_xor_sync(0xFFFFFFFFu, s1, o);
    }
    if (lane == 0) {
        int sl = (s0 + bt[0] >= s1 + bt[1]) ? 1 : 0;
        g_sel[n] = sl;
        int isleaf = (n >= NINT) ? 1 : 0;
        int cls = sl * 2 + isleaf;
        int pos = atomicAdd(&g_gcnt[cls], 1);
        g_gidx[cls][pos] = n;
        if (!isleaf) {
            const int STc[8] = {0, 1, 5, 21, 85, 341, 1365, 5461};
            int l = 0;
            while (n >= STc[l + 1]) l++;
            int pos2 = atomicAdd(&g_lcnt[2 * l + sl], 1);
            int* arr = sl ? g_lidx_l : g_lidx_v;
            arr[STc[l] + pos2] = n;
        }
    }
}

// ---------------- h / hsum writers ([hi|lo] split) ----------------
__device__ __forceinline__ void write_h(int n, int j, float h, float* __restrict__ h_out) {
    h_out[(size_t)n * DIM + j] = h;
    __nv_bfloat16 hh, hl;
    bsplit(h, hh, hl);
    size_t b = (size_t)n * KPS + j;
    g_hsplit[b]       = hh;
    g_hsplit[b + 512] = hl;
}
__device__ __forceinline__ void write_hsum(int q, int j, float s) {
    __nv_bfloat16 hh, hl;
    bsplit(s, hh, hl);
    size_t bb = (size_t)q * KPS + j;
    g_hsumsplit[bb]       = hh;
    g_hsumsplit[bb + 512] = hl;
}

// ---------------- leaves (4 siblings/thread) + fused hsum for level 5 ----------------
__global__ void leaf_hsum(const float* __restrict__ bi_v,
                          const float* __restrict__ bi_l,
                          float* __restrict__ h_out)
{
    int idx = blockIdx.x * blockDim.x + threadIdx.x;   // q*512 + j
    if (idx >= (NLEAF / 4) * DIM) return;
    int q = idx >> 9, j = idx & (DIM - 1);
    float hs = 0.f;
#pragma unroll
    for (int r = 0; r < 4; r++) {
        int n = LEAF_START + 4 * q + r;
        const float* bi = g_sel[n] ? bi_l : bi_v;
        size_t base = (size_t)n * 2048;
        float ig = g_pre[base + j]        + bi[j];
        float og = g_pre[base + 512 + j]  + bi[512 + j];
        float ug = g_pre[base + 1024 + j] + bi[1024 + j];
        float cc = sigmf(ig) * tanhfast(ug);
        float hh = sigmf(og) * tanhfast(cc);
        g_c[(size_t)n * DIM + j] = cc;
        write_h(n, j, hh, h_out);
        hs += hh;
    }
    write_hsum(q, j, hs);
}

// ---------------- gates (4 siblings/thread) + fused hsum for level-1 ----------------
__global__ void gates_hsum(int s, int S1, int E, int do_hsum,
                           const float* __restrict__ bi_v,
                           const float* __restrict__ bi_l,
                           const float* __restrict__ bf_v,
                           const float* __restrict__ bf_l,
                           float* __restrict__ h_out)
{
    int nG = (E >= 4) ? (E >> 2) : 1;
    int rcnt = (E >= 4) ? 4 : E;
    int idx = blockIdx.x * blockDim.x + threadIdx.x;
    if (idx >= nG * DIM) return;
    int q = idx >> 9, j = idx & (DIM - 1);
    float hs = 0.f;
#pragma unroll 4
    for (int r = 0; r < rcnt; r++) {
        int i = (rcnt == 4) ? (4 * q + r) : r;
        int n = s + i;
        int sl = g_sel[n];
        const float* bi = sl ? bi_l : bi_v;
        const float* bf = sl ? bf_l : bf_v;
        size_t xb = (size_t)n * 2048;
        size_t hb = (size_t)i * 1536;
        float ig = g_pre[xb + j]        + g_hsiou[hb + j]        + bi[j];
        float og = g_pre[xb + 512 + j]  + g_hsiou[hb + 512 + j]  + bi[512 + j];
        float ug = g_pre[xb + 1024 + j] + g_hsiou[hb + 1024 + j] + bi[1024 + j];
        float fxv = g_pre[xb + 1536 + j] + bf[j];

        float cc = sigmf(ig) * tanhfast(ug);
        size_t c0 = (size_t)(S1 + 4 * i) * DIM + j;
        size_t f0 = (size_t)(4 * i) * 512 + j;
#pragma unroll
        for (int k = 0; k < 4; k++) {
            float f = sigmf(g_fh[f0 + (size_t)k * 512] + fxv);
            cc = fmaf(f, g_c[c0 + (size_t)k * DIM], cc);
        }
        float hh = sigmf(og) * tanhfast(cc);
        g_c[(size_t)n * DIM + j] = cc;
        write_h(n, j, hh, h_out);
        hs += hh;
    }
    if (do_hsum) write_hsum(q, j, hs);
}

// ---------------- launch ----------------
extern "C" void kernel_launch(void* const* d_in, const int* in_sizes, int n_in,
                              void* d_out, int out_size)
{
    const float* x        = (const float*)d_in[0];
    const float* W_ioux_v = (const float*)d_in[2];
    const float* b_ioux_v = (const float*)d_in[3];
    const float* W_iouh_v = (const float*)d_in[4];
    const float* b_iouh_v = (const float*)d_in[5];
    const float* W_fx_v   = (const float*)d_in[6];
    const float* b_fx_v   = (const float*)d_in[7];
    const float* W_fh_v   = (const float*)d_in[8];
    const float* b_fh_v   = (const float*)d_in[9];
    const float* W_ioux_l = (const float*)d_in[10];
    const float* b_ioux_l = (const float*)d_in[11];
    const float* W_iouh_l = (const float*)d_in[12];
    const float* b_iouh_l = (const float*)d_in[13];
    const float* W_fx_l   = (const float*)d_in[14];
    const float* b_fx_l   = (const float*)d_in[15];
    const float* W_fh_l   = (const float*)d_in[16];
    const float* b_fh_l   = (const float*)d_in[17];
    const float* W_type   = (const float*)d_in[18];
    const float* b_type   = (const float*)d_in[19];
    float* h_out = (float*)d_out;

    cudaFuncSetAttribute(gemm_big, cudaFuncAttributeMaxDynamicSharedMemorySize, SMEM_BIG);
    cudaFuncSetAttribute(gemm_lvl, cudaFuncAttributeMaxDynamicSharedMemorySize, SMEM_LVL);

    __nv_bfloat16 *p_xsplit, *p_hsplit, *p_hsumsplit, *p_Wmod, *p_Wiouh, *p_Wfh;
    float *p_bmod, *p_pre, *p_hsiou, *p_fh;
    int *p_gcnt, *p_gidx, *p_lcnt, *p_lidx_v, *p_lidx_l;
    cudaGetSymbolAddress((void**)&p_xsplit,    g_xsplit);
    cudaGetSymbolAddress((void**)&p_hsplit,    g_hsplit);
    cudaGetSymbolAddress((void**)&p_hsumsplit, g_hsumsplit);
    cudaGetSymbolAddress((void**)&p_Wmod,      g_Wmod);
    cudaGetSymbolAddress((void**)&p_Wiouh,     g_Wiouh_m);
    cudaGetSymbolAddress((void**)&p_Wfh,       g_Wfh_m);
    cudaGetSymbolAddress((void**)&p_bmod,      g_bmod);
    cudaGetSymbolAddress((void**)&p_pre,       g_pre);
    cudaGetSymbolAddress((void**)&p_hsiou,     g_hsiou);
    cudaGetSymbolAddress((void**)&p_fh,        g_fh);
    cudaGetSymbolAddress((void**)&p_gcnt,      g_gcnt);
    cudaGetSymbolAddress((void**)&p_gidx,      g_gidx);
    cudaGetSymbolAddress((void**)&p_lcnt,      g_lcnt);
    cudaGetSymbolAddress((void**)&p_lidx_v,    g_lidx_v);
    cudaGetSymbolAddress((void**)&p_lidx_l,    g_lidx_l);

    zero_cnt<<<1, 32>>>();
    sel_group<<<(NNODES + 7) / 8, 256>>>(x, W_type, b_type);
    pack_all<<<(PACK_TOTAL + 255) / 256, 256>>>(
        x, W_ioux_v, W_ioux_l, W_fx_v, W_fx_l, W_iouh_v, W_iouh_l, W_fh_v, W_fh_l,
        b_ioux_v, b_ioux_l, b_fx_v, b_fx_l);

    // big precompute GEMM (BN=128)
    {
        GDesc4 dd;
        for (int m = 0; m < 2; m++) {
            for (int lf = 0; lf < 2; lf++) {
                GDesc& d = dd.d[2 * m + lf];
                d.A = p_xsplit;
                d.B = p_Wmod + (size_t)m * 2048 * KPS;
                d.bias = p_bmod + (size_t)m * 2048;
                d.C = p_pre;
                d.cnt = p_gcnt + 2 * m + lf;
                d.idx = p_gidx + (2 * m + lf) * NNODES;
                d.child4 = 0; d.sub = 0; d.csub = 0; d.ldc = 2048;
                d.Nc = lf ? 1536 : 2048;
            }
        }
        gemm_big<<<dim3(2048 / 128, 32, 4), 256, SMEM_BIG>>>(dd);
    }

    // leaves + fused hsum for level 5
    leaf_hsum<<<((NLEAF / 4) * DIM) / 256, 256>>>(b_iouh_v, b_iouh_l, h_out);

    static const int ST[8] = {0, 1, 5, 21, 85, 341, 1365, 5461};
    for (int l = 5; l >= 0; --l) {
        int s  = ST[l];
        int S1 = ST[l + 1];
        int E  = ST[l + 1] - ST[l];

        GDesc4 dd;
        for (int m = 0; m < 2; m++) {
            const int* lidx = (m ? p_lidx_l : p_lidx_v) + s;
            const int* lcnt = p_lcnt + 2 * l + m;
            GDesc& di = dd.d[2 * m];
            di.A = p_hsumsplit;
            di.B = p_Wiouh + (size_t)m * 1536 * KPS;
            di.bias = nullptr;
            di.C = p_hsiou;
            di.cnt = lcnt; di.idx = lidx;
            di.child4 = 0; di.sub = s; di.csub = 0; di.ldc = 1536; di.Nc = 1536;
            GDesc& df = dd.d[2 * m + 1];
            df.A = p_hsplit;
            df.B = p_Wfh + (size_t)m * 512 * KPS;
            df.bias = nullptr;
            df.C = p_fh;
            df.cnt = lcnt; df.idx = lidx;
            df.child4 = 1; df.sub = 0; df.csub = S1; df.ldc = 512; df.Nc = 512;
        }
        int ytiles = (4 * E + 127) / 128;
        gemm_lvl<<<dim3(1536 / 64, ytiles, 4), 256, SMEM_LVL>>>(dd);

        int nG = (E >= 4) ? (E / 4) : 1;
        gates_hsum<<<(nG * DIM + 255) / 256, 256>>>(
            s, S1, E, l > 0 ? 1 : 0, b_iouh_v, b_iouh_l, b_fh_v, b_fh_l, h_out);
    }
}

// round 17
// speedup vs baseline: 1.0543x; 1.0543x over previous
#include <cuda_runtime.h>
#include <cuda_bf16.h>
#include <math.h>
#include <stdint.h>

#define NNODES 5461
#define NINT 1365
#define LEAF_START 1365
#define NLEAF 4096
#define DIM 512
#define KPS 1024          // stored split rows: A=[hi|lo], B=[Wh|Wl]
#define BKC 64
#define NIT 24            // logical K' = 1536 = 24 chunks of 64

// ---------------- scratch ----------------
__device__ __align__(16) __nv_bfloat16 g_xsplit[(size_t)NNODES * KPS];
__device__ __align__(16) __nv_bfloat16 g_hsplit[(size_t)NNODES * KPS];
__device__ __align__(16) __nv_bfloat16 g_hsumsplit[1024 * KPS];
__device__ __align__(16) __nv_bfloat16 g_Wmod[2][2048 * KPS];
__device__ __align__(16) __nv_bfloat16 g_Wiouh_m[2][1536 * KPS];
__device__ __align__(16) __nv_bfloat16 g_Wfh_m[2][512 * KPS];
__device__ float g_bmod[2][2048];
__device__ float g_pre[(size_t)NNODES * 2048];
__device__ float g_hsiou[1024 * 1536];
__device__ float g_fh[4096 * 512];
__device__ float g_c[NNODES * DIM];
__device__ int   g_sel[NNODES];
__device__ int   g_gcnt[4];              // zero-init at load; re-zeroed by final gates
__device__ int   g_gidx[4][NNODES];
__device__ int   g_lcnt[12];
__device__ int   g_lidx_v[NINT];
__device__ int   g_lidx_l[NINT];

// fast activations (MUFU-only; ~1e-7 rel err vs 1e-3 tolerance)
__device__ __forceinline__ float sigmf(float x) { return 1.0f / (1.0f + __expf(-x)); }
__device__ __forceinline__ float tanhfast(float x) {
    return 2.0f / (1.0f + __expf(-2.0f * x)) - 1.0f;
}

// ---------------- PTX helpers ----------------
__device__ __forceinline__ uint32_t smem_u32(const void* p) {
    uint32_t a;
    asm("{ .reg .u64 t; cvta.to.shared.u64 t, %1; cvt.u32.u64 %0, t; }" : "=r"(a) : "l"(p));
    return a;
}
__device__ __forceinline__ void cpasync16(uint32_t dst, const void* src, int srcsize) {
    asm volatile("cp.async.cg.shared.global [%0], [%1], 16, %2;"
                 :: "r"(dst), "l"(src), "r"(srcsize) : "memory");
}
#define CP_COMMIT() asm volatile("cp.async.commit_group;" ::: "memory")
#define CP_WAIT1()  asm volatile("cp.async.wait_group 1;" ::: "memory")
#define CP_WAIT0()  asm volatile("cp.async.wait_group 0;" ::: "memory")

#define LDSM4(r, addr) \
    asm volatile("ldmatrix.sync.aligned.m8n8.x4.shared.b16 {%0,%1,%2,%3}, [%4];" \
                 : "=r"((r)[0]), "=r"((r)[1]), "=r"((r)[2]), "=r"((r)[3]) : "r"(addr))

#define MMA16816(d, a, b0_, b1_) \
    asm volatile("mma.sync.aligned.m16n8k16.row.col.f32.bf16.bf16.f32 " \
                 "{%0,%1,%2,%3}, {%4,%5,%6,%7}, {%8,%9}, {%0,%1,%2,%3};" \
                 : "+f"((d)[0]), "+f"((d)[1]), "+f"((d)[2]), "+f"((d)[3]) \
                 : "r"((a)[0]), "r"((a)[1]), "r"((a)[2]), "r"((a)[3]), "r"(b0_), "r"(b1_))

__device__ __forceinline__ uint32_t sw128(uint32_t off) {
    return off ^ ((off >> 3) & 0x70);
}
__device__ __forceinline__ void bsplit(float v, __nv_bfloat16& h, __nv_bfloat16& l) {
    h = __float2bfloat16(v);
    l = __float2bfloat16(v - __bfloat162float(h));
}

// ---------------- GEMM descriptors ----------------
struct GDesc {
    const __nv_bfloat16* A;
    const __nv_bfloat16* B;
    const float* bias;
    float* C;
    const int* cnt;
    const int* idx;
    int child4, sub, csub, ldc, Nc;
};
struct GDesc4 { GDesc d[4]; };

// ---------------- gemm_big: BM=128 BN=128, 2 CTAs/SM ----------------
#define TILE_BYTES_BIG 16384
#define SMEM_BIG (4 * TILE_BYTES_BIG)

__global__ void __launch_bounds__(256, 2) gemm_big(GDesc4 dd)
{
    const GDesc ds = dd.d[blockIdx.z];
    const int Nc = ds.Nc;
    const int col0 = blockIdx.x * 128;
    if (col0 >= Nc) return;
    const int nlist = *ds.cnt;
    const int Mrows = ds.child4 ? 4 * nlist : nlist;
    const int row0 = blockIdx.y * 128;
    if (row0 >= Mrows) return;

    extern __shared__ char smem[];
    const uint32_t sb = smem_u32(smem);
    const int tid  = threadIdx.x;
    const int wid  = tid >> 5;
    const int lane = tid & 31;
    const int wm   = wid & 3;
    const int wn   = wid >> 2;

    const int lrow = tid >> 1;
    const int lch0 = (tid & 1) * 4;
    const int g = row0 + lrow;
    int nodeA = 0, a_sz = 0;
    if (g < Mrows) {
        nodeA = ds.child4 ? (4 * ds.idx[g >> 2] + 1 + (g & 3)) : (ds.idx[g] - ds.sub);
        a_sz = 16;
    }
    const __nv_bfloat16* gA = ds.A + (size_t)nodeA * KPS + lch0 * 8;
    const __nv_bfloat16* gB = ds.B + (size_t)(col0 + lrow) * KPS + lch0 * 8;
    uint32_t sA[4], sB[4];
#pragma unroll
    for (int i = 0; i < 4; i++) {
        uint32_t off = sw128((uint32_t)(lrow * 128 + (lch0 + i) * 16));
        sA[i] = sb + off;
        sB[i] = sb + 2 * TILE_BYTES_BIG + off;
    }

    uint32_t rawA[2], rawB[4];
#pragma unroll
    for (int mi = 0; mi < 2; mi++)
        rawA[mi] = (uint32_t)((wm * 32 + mi * 16 + (lane & 15)) * 128 + ((lane >> 4) << 4));
#pragma unroll
    for (int ni = 0; ni < 4; ni++)
        rawB[ni] = (uint32_t)((wn * 64 + ni * 16 + (lane & 7) + ((lane >> 4) << 3)) * 128
                              + (((lane >> 3) & 1) << 4));

    float acc[2][8][4];
#pragma unroll
    for (int mi = 0; mi < 2; mi++)
#pragma unroll
        for (int nj = 0; nj < 8; nj++)
#pragma unroll
            for (int q = 0; q < 4; q++) acc[mi][nj][q] = 0.f;

    auto loadc = [&](int c, uint32_t bsel) {
        int cA = (c < 16) ? c : c - 16;
        int cB = (c < 8)  ? c : c - 8;
        const __nv_bfloat16* pa = gA + cA * BKC;
        const __nv_bfloat16* pb = gB + cB * BKC;
#pragma unroll
        for (int i = 0; i < 4; i++) {
            cpasync16(sA[i] + bsel, pa + i * 8, a_sz);
            cpasync16(sB[i] + bsel, pb + i * 8, 16);
        }
    };

    loadc(0, 0);
    CP_COMMIT();

    for (int c = 0; c < NIT; c++) {
        if (c + 1 < NIT) {
            loadc(c + 1, ((c + 1) & 1) * TILE_BYTES_BIG);
            CP_COMMIT();
            CP_WAIT1();
        } else {
            CP_WAIT0();
        }
        __syncthreads();

        const uint32_t abase = sb + (c & 1) * TILE_BYTES_BIG;
        const uint32_t bbase = sb + 2 * TILE_BYTES_BIG + (c & 1) * TILE_BYTES_BIG;
#pragma unroll
        for (int kb = 0; kb < 4; kb++) {
            const uint32_t kby = (uint32_t)(kb * 32);
            uint32_t a0[4], a1[4];
            LDSM4(a0, abase + sw128(rawA[0] + kby));
            LDSM4(a1, abase + sw128(rawA[1] + kby));
#pragma unroll
            for (int ni = 0; ni < 4; ni++) {
                uint32_t bt[4];
                LDSM4(bt, bbase + sw128(rawB[ni] + kby));
                MMA16816(acc[0][2 * ni],     a0, bt[0], bt[1]);
                MMA16816(acc[0][2 * ni + 1], a0, bt[2], bt[3]);
                MMA16816(acc[1][2 * ni],     a1, bt[0], bt[1]);
                MMA16816(acc[1][2 * ni + 1], a1, bt[2], bt[3]);
            }
        }
        __syncthreads();
    }

#pragma unroll
    for (int mi = 0; mi < 2; mi++) {
        int rbase = row0 + wm * 32 + mi * 16 + (lane >> 2);
#pragma unroll
        for (int half = 0; half < 2; half++) {
            int r = rbase + half * 8;
            if (r >= Mrows) continue;
            int node = ds.child4 ? (4 * ds.idx[r >> 2] + 1 + (r & 3)) : (ds.idx[r] - ds.sub);
            float* Crow = ds.C + (size_t)(node - ds.csub) * ds.ldc;
#pragma unroll
            for (int nj = 0; nj < 8; nj++) {
                int col = col0 + wn * 64 + nj * 8 + (lane & 3) * 2;
                float b0 = 0.f, b1 = 0.f;
                if (ds.bias) { b0 = ds.bias[col]; b1 = ds.bias[col + 1]; }
                float2 v = make_float2(acc[mi][nj][2 * half] + b0, acc[mi][nj][2 * half + 1] + b1);
                *(float2*)(Crow + col) = v;
            }
        }
    }
}

// ---------------- gemm_lvl: BM=128 BN=64, 3 CTAs/SM ----------------
#define A_TILE_BYTES 16384
#define B_TILE_BYTES 8192
#define SMEM_LVL (2 * A_TILE_BYTES + 2 * B_TILE_BYTES)   // 48 KB

__global__ void __launch_bounds__(256, 3) gemm_lvl(GDesc4 dd)
{
    const GDesc ds = dd.d[blockIdx.z];
    const int Nc = ds.Nc;
    const int col0 = blockIdx.x * 64;
    if (col0 >= Nc) return;
    const int nlist = *ds.cnt;
    const int Mrows = ds.child4 ? 4 * nlist : nlist;
    const int row0 = blockIdx.y * 128;
    if (row0 >= Mrows) return;

    extern __shared__ char smem[];
    const uint32_t sb = smem_u32(smem);
    const int tid  = threadIdx.x;
    const int wid  = tid >> 5;
    const int lane = tid & 31;
    const int wm   = wid & 3;
    const int wn   = wid >> 2;

    const int lrow = tid >> 1;
    const int lch0 = (tid & 1) * 4;
    const int g = row0 + lrow;
    int nodeA = 0, a_sz = 0;
    if (g < Mrows) {
        nodeA = ds.child4 ? (4 * ds.idx[g >> 2] + 1 + (g & 3)) : (ds.idx[g] - ds.sub);
        a_sz = 16;
    }
    const __nv_bfloat16* gA = ds.A + (size_t)nodeA * KPS + lch0 * 8;
    uint32_t sA[4];
#pragma unroll
    for (int i = 0; i < 4; i++)
        sA[i] = sb + sw128((uint32_t)(lrow * 128 + (lch0 + i) * 16));

    const int browB = tid >> 2;
    const int bch0  = (tid & 3) * 2;
    const __nv_bfloat16* gB = ds.B + (size_t)(col0 + browB) * KPS + bch0 * 8;
    uint32_t sB[2];
#pragma unroll
    for (int i = 0; i < 2; i++)
        sB[i] = sb + 2 * A_TILE_BYTES + sw128((uint32_t)(browB * 128 + (bch0 + i) * 16));

    uint32_t rawA[2], rawB[2];
#pragma unroll
    for (int mi = 0; mi < 2; mi++)
        rawA[mi] = (uint32_t)((wm * 32 + mi * 16 + (lane & 15)) * 128 + ((lane >> 4) << 4));
#pragma unroll
    for (int ni = 0; ni < 2; ni++)
        rawB[ni] = (uint32_t)((wn * 32 + ni * 16 + (lane & 7) + ((lane >> 4) << 3)) * 128
                              + (((lane >> 3) & 1) << 4));

    float acc[2][4][4];
#pragma unroll
    for (int mi = 0; mi < 2; mi++)
#pragma unroll
        for (int nj = 0; nj < 4; nj++)
#pragma unroll
            for (int q = 0; q < 4; q++) acc[mi][nj][q] = 0.f;

    auto loadc = [&](int c, int buf) {
        int cA = (c < 16) ? c : c - 16;
        int cB = (c < 8)  ? c : c - 8;
        const __nv_bfloat16* pa = gA + cA * BKC;
        const __nv_bfloat16* pb = gB + cB * BKC;
        uint32_t aoff = (uint32_t)buf * A_TILE_BYTES;
        uint32_t boff = (uint32_t)buf * B_TILE_BYTES;
#pragma unroll
        for (int i = 0; i < 4; i++) cpasync16(sA[i] + aoff, pa + i * 8, a_sz);
#pragma unroll
        for (int i = 0; i < 2; i++) cpasync16(sB[i] + boff, pb + i * 8, 16);
    };

    loadc(0, 0);
    CP_COMMIT();

    for (int c = 0; c < NIT; c++) {
        if (c + 1 < NIT) {
            loadc(c + 1, (c + 1) & 1);
            CP_COMMIT();
            CP_WAIT1();
        } else {
            CP_WAIT0();
        }
        __syncthreads();

        const uint32_t abase = sb + (c & 1) * A_TILE_BYTES;
        const uint32_t bbase = sb + 2 * A_TILE_BYTES + (c & 1) * B_TILE_BYTES;
#pragma unroll
        for (int kb = 0; kb < 4; kb++) {
            const uint32_t kby = (uint32_t)(kb * 32);
            uint32_t a0[4], a1[4];
            LDSM4(a0, abase + sw128(rawA[0] + kby));
            LDSM4(a1, abase + sw128(rawA[1] + kby));
#pragma unroll
            for (int ni = 0; ni < 2; ni++) {
                uint32_t bt[4];
                LDSM4(bt, bbase + sw128(rawB[ni] + kby));
                MMA16816(acc[0][2 * ni],     a0, bt[0], bt[1]);
                MMA16816(acc[0][2 * ni + 1], a0, bt[2], bt[3]);
                MMA16816(acc[1][2 * ni],     a1, bt[0], bt[1]);
                MMA16816(acc[1][2 * ni + 1], a1, bt[2], bt[3]);
            }
        }
        __syncthreads();
    }

#pragma unroll
    for (int mi = 0; mi < 2; mi++) {
        int rbase = row0 + wm * 32 + mi * 16 + (lane >> 2);
#pragma unroll
        for (int half = 0; half < 2; half++) {
            int r = rbase + half * 8;
            if (r >= Mrows) continue;
            int node = ds.child4 ? (4 * ds.idx[r >> 2] + 1 + (r & 3)) : (ds.idx[r] - ds.sub);
            float* Crow = ds.C + (size_t)(node - ds.csub) * ds.ldc;
#pragma unroll
            for (int nj = 0; nj < 4; nj++) {
                int col = col0 + wn * 32 + nj * 8 + (lane & 3) * 2;
                float b0 = 0.f, b1 = 0.f;
                if (ds.bias) { b0 = ds.bias[col]; b1 = ds.bias[col + 1]; }
                float2 v = make_float2(acc[mi][nj][2 * half] + b0, acc[mi][nj][2 * half + 1] + b1);
                *(float2*)(Crow + col) = v;
            }
        }
    }
}

// ---------------- fused preprocessing: pack weights (3 sets) + split x ----------------
#define R0 (2 * 2048 * 64)
#define R1 (2 * 1536 * 64)
#define R2 (2 * 512 * 64)
#define R3 (NNODES * 64)
#define PACK_TOTAL (R0 + R1 + R2 + R3)

__global__ void pack_all(const float* __restrict__ x,
                         const float* __restrict__ Wi_v, const float* __restrict__ Wi_l,
                         const float* __restrict__ Wf_v, const float* __restrict__ Wf_l,
                         const float* __restrict__ Wh_v, const float* __restrict__ Wh_l,
                         const float* __restrict__ Wfh_v, const float* __restrict__ Wfh_l,
                         const float* __restrict__ bi_v, const float* __restrict__ bi_l,
                         const float* __restrict__ bf_v, const float* __restrict__ bf_l)
{
    int idx = blockIdx.x * blockDim.x + threadIdx.x;
    if (idx >= PACK_TOTAL) return;

    if (idx < R0) {
        int m  = idx >> 17;
        int rem = idx & 131071;
        int kb = rem >> 11;
        int n  = rem & 2047;
        const float* W; int col, ld;
        if (n < 1536) { W = m ? Wi_l : Wi_v; col = n;        ld = 1536; }
        else          { W = m ? Wf_l : Wf_v; col = n - 1536; ld = 512;  }
        __nv_bfloat16 hi8[8], lo8[8];
#pragma unroll
        for (int j = 0; j < 8; j++) bsplit(W[(size_t)(kb * 8 + j) * ld + col], hi8[j], lo8[j]);
        __nv_bfloat16* dst = g_Wmod[m];
        size_t b = (size_t)n * KPS + kb * 8;
        *(uint4*)&dst[b]       = *(uint4*)hi8;
        *(uint4*)&dst[b + 512] = *(uint4*)lo8;
        if (kb == 0) {
            float bv;
            if (n < 1536) bv = m ? bi_l[n] : bi_v[n];
            else          bv = m ? bf_l[n - 1536] : bf_v[n - 1536];
            g_bmod[m][n] = bv;
        }
        return;
    }
    idx -= R0;
    if (idx < R1) {
        const int rows = 1536;
        int m  = idx / (rows * 64);
        int rem = idx - m * rows * 64;
        int kb = rem / rows;
        int n  = rem - kb * rows;
        const float* W = m ? Wh_l : Wh_v;
        __nv_bfloat16 hi8[8], lo8[8];
#pragma unroll
        for (int j = 0; j < 8; j++) bsplit(W[(size_t)(kb * 8 + j) * rows + n], hi8[j], lo8[j]);
        __nv_bfloat16* dst = &g_Wiouh_m[0][0];
        size_t b = (size_t)m * rows * KPS + (size_t)n * KPS + kb * 8;
        *(uint4*)&dst[b]       = *(uint4*)hi8;
        *(uint4*)&dst[b + 512] = *(uint4*)lo8;
        return;
    }
    idx -= R1;
    if (idx < R2) {
        const int rows = 512;
        int m  = idx / (rows * 64);
        int rem = idx - m * rows * 64;
        int kb = rem / rows;
        int n  = rem - kb * rows;
        const float* W = m ? Wfh_l : Wfh_v;
        __nv_bfloat16 hi8[8], lo8[8];
#pragma unroll
        for (int j = 0; j < 8; j++) bsplit(W[(size_t)(kb * 8 + j) * rows + n], hi8[j], lo8[j]);
        __nv_bfloat16* dst = &g_Wfh_m[0][0];
        size_t b = (size_t)m * rows * KPS + (size_t)n * KPS + kb * 8;
        *(uint4*)&dst[b]       = *(uint4*)hi8;
        *(uint4*)&dst[b + 512] = *(uint4*)lo8;
        return;
    }
    idx -= R2;
    {
        int n = idx >> 6, kb = idx & 63;
        __nv_bfloat16 hi8[8], lo8[8];
        const float* p = x + (size_t)n * DIM + kb * 8;
#pragma unroll
        for (int j = 0; j < 8; j++) bsplit(p[j], hi8[j], lo8[j]);
        size_t b = (size_t)n * KPS + kb * 8;
        *(uint4*)&g_xsplit[b]       = *(uint4*)hi8;
        *(uint4*)&g_xsplit[b + 512] = *(uint4*)lo8;
    }
}

// ---------------- selection + grouping (fused) ----------------
__global__ void sel_group(const float* __restrict__ x,
                          const float* __restrict__ Wt,
                          const float* __restrict__ bt)
{
    int n = blockIdx.x * (blockDim.x >> 5) + (threadIdx.x >> 5);
    int lane = threadIdx.x & 31;
    if (n >= NNODES) return;
    float s0 = 0.f, s1 = 0.f;
    const float* xr = x + (size_t)n * DIM;
#pragma unroll 4
    for (int k = lane; k < DIM; k += 32) {
        float xv = xr[k];
        s0 = fmaf(xv, Wt[k * 2 + 0], s0);
        s1 = fmaf(xv, Wt[k * 2 + 1], s1);
    }
#pragma unroll
    for (int o = 16; o > 0; o >>= 1) {
        s0 += __shfl_xor_sync(0xFFFFFFFFu, s0, o);
        s1 += __shfl_xor_sync(0xFFFFFFFFu, s1, o);
    }
    if (lane == 0) {
        int sl = (s0 + bt[0] >= s1 + bt[1]) ? 1 : 0;
        g_sel[n] = sl;
        int isleaf = (n >= NINT) ? 1 : 0;
        int cls = sl * 2 + isleaf;
        int pos = atomicAdd(&g_gcnt[cls], 1);
        g_gidx[cls][pos] = n;
        if (!isleaf) {
            const int STc[8] = {0, 1, 5, 21, 85, 341, 1365, 5461};
            int l = 0;
            while (n >= STc[l + 1]) l++;
            int pos2 = atomicAdd(&g_lcnt[2 * l + sl], 1);
            int* arr = sl ? g_lidx_l : g_lidx_v;
            arr[STc[l] + pos2] = n;
        }
    }
}

// ---------------- h write + split ([hi|lo]), 2 columns ----------------
__device__ __forceinline__ void write_h2(int n, int jj, float h0, float h1,
                                         float* __restrict__ h_out) {
    *(float2*)&h_out[(size_t)n * DIM + jj] = make_float2(h0, h1);
    __nv_bfloat16 hh0, hl0, hh1, hl1;
    bsplit(h0, hh0, hl0);
    bsplit(h1, hh1, hl1);
    size_t b = (size_t)n * KPS + jj;
    __nv_bfloat162 hv; hv.x = hh0; hv.y = hh1;
    __nv_bfloat162 lv; lv.x = hl0; lv.y = hl1;
    *(__nv_bfloat162*)&g_hsplit[b]       = hv;
    *(__nv_bfloat162*)&g_hsplit[b + 512] = lv;
}

// ---------------- leaves (float2) ----------------
__global__ void leaf_kernel(const float* __restrict__ bi_v,
                            const float* __restrict__ bi_l,
                            float* __restrict__ h_out)
{
    int idx = blockIdx.x * blockDim.x + threadIdx.x;
    if (idx >= NLEAF * 256) return;
    int n = LEAF_START + (idx >> 8);
    int jj = (idx & 255) * 2;
    const float* bi = g_sel[n] ? bi_l : bi_v;
    size_t base = (size_t)n * 2048;
    float2 ix = *(const float2*)&g_pre[base + jj];
    float2 ox = *(const float2*)&g_pre[base + 512 + jj];
    float2 ux = *(const float2*)&g_pre[base + 1024 + jj];
    float2 bI = *(const float2*)&bi[jj];
    float2 bO = *(const float2*)&bi[512 + jj];
    float2 bU = *(const float2*)&bi[1024 + jj];
    float cc0 = sigmf(ix.x + bI.x) * tanhfast(ux.x + bU.x);
    float cc1 = sigmf(ix.y + bI.y) * tanhfast(ux.y + bU.y);
    float hh0 = sigmf(ox.x + bO.x) * tanhfast(cc0);
    float hh1 = sigmf(ox.y + bO.y) * tanhfast(cc1);
    *(float2*)&g_c[(size_t)n * DIM + jj] = make_float2(cc0, cc1);
    write_h2(n, jj, hh0, hh1, h_out);
}

// ---------------- h_sum + split (float2) ----------------
__global__ void hsum_kernel(const float* __restrict__ h_all, int S1, int E)
{
    int idx = blockIdx.x * blockDim.x + threadIdx.x;
    if (idx >= E * 256) return;
    int i = idx >> 8, jj = (idx & 255) * 2;
    const float* b = h_all + (size_t)(S1 + 4 * i) * DIM + jj;
    float2 v0 = *(const float2*)(b);
    float2 v1 = *(const float2*)(b + DIM);
    float2 v2 = *(const float2*)(b + 2 * DIM);
    float2 v3 = *(const float2*)(b + 3 * DIM);
    float s0 = (v0.x + v1.x) + (v2.x + v3.x);
    float s1 = (v0.y + v1.y) + (v2.y + v3.y);
    __nv_bfloat16 hh0, hl0, hh1, hl1;
    bsplit(s0, hh0, hl0);
    bsplit(s1, hh1, hl1);
    size_t bb = (size_t)i * KPS + jj;
    __nv_bfloat162 hv; hv.x = hh0; hv.y = hh1;
    __nv_bfloat162 lv; lv.x = hl0; lv.y = hl1;
    *(__nv_bfloat162*)&g_hsumsplit[bb]       = hv;
    *(__nv_bfloat162*)&g_hsumsplit[bb + 512] = lv;
}

// ---------------- internal-node gates (float2) ----------------
__global__ void gates_kernel(int s, int S1, int E,
                             const float* __restrict__ bi_v,
                             const float* __restrict__ bi_l,
                             const float* __restrict__ bf_v,
                             const float* __restrict__ bf_l,
                             float* __restrict__ h_out)
{
    // re-zero grouping counters for the next graph replay (level 0 only;
    // all counter consumers completed earlier in stream order)
    if (s == 0 && blockIdx.x == 0) {
        int t = threadIdx.x;
        if (t < 4)  g_gcnt[t] = 0;
        if (t < 12) g_lcnt[t] = 0;
    }
    int idx = blockIdx.x * blockDim.x + threadIdx.x;
    if (idx >= E * 256) return;
    int i = idx >> 8, jj = (idx & 255) * 2;
    int n = s + i;
    int sl = g_sel[n];
    const float* bi = sl ? bi_l : bi_v;
    const float* bf = sl ? bf_l : bf_v;
    size_t xb = (size_t)n * 2048;
    size_t hb = (size_t)i * 1536;
    float2 ix = *(const float2*)&g_pre[xb + jj];
    float2 ox = *(const float2*)&g_pre[xb + 512 + jj];
    float2 ux = *(const float2*)&g_pre[xb + 1024 + jj];
    float2 fx = *(const float2*)&g_pre[xb + 1536 + jj];
    float2 ih = *(const float2*)&g_hsiou[hb + jj];
    float2 oh = *(const float2*)&g_hsiou[hb + 512 + jj];
    float2 uh = *(const float2*)&g_hsiou[hb + 1024 + jj];
    float2 bI = *(const float2*)&bi[jj];
    float2 bO = *(const float2*)&bi[512 + jj];
    float2 bU = *(const float2*)&bi[1024 + jj];
    float2 bF = *(const float2*)&bf[jj];

    float fxv0 = fx.x + bF.x;
    float fxv1 = fx.y + bF.y;
    float cc0 = sigmf(ix.x + ih.x + bI.x) * tanhfast(ux.x + uh.x + bU.x);
    float cc1 = sigmf(ix.y + ih.y + bI.y) * tanhfast(ux.y + uh.y + bU.y);
    size_t c0 = (size_t)(S1 + 4 * i) * DIM + jj;
    size_t f0 = (size_t)(4 * i) * 512 + jj;
#pragma unroll
    for (int k = 0; k < 4; k++) {
        float2 fh2 = *(const float2*)&g_fh[f0 + (size_t)k * 512];
        float2 cv  = *(const float2*)&g_c[c0 + (size_t)k * DIM];
        cc0 = fmaf(sigmf(fh2.x + fxv0), cv.x, cc0);
        cc1 = fmaf(sigmf(fh2.y + fxv1), cv.y, cc1);
    }
    float hh0 = sigmf(ox.x + oh.x + bO.x) * tanhfast(cc0);
    float hh1 = sigmf(ox.y + oh.y + bO.y) * tanhfast(cc1);
    *(float2*)&g_c[(size_t)n * DIM + jj] = make_float2(cc0, cc1);
    write_h2(n, jj, hh0, hh1, h_out);
}

// ---------------- launch ----------------
extern "C" void kernel_launch(void* const* d_in, const int* in_sizes, int n_in,
                              void* d_out, int out_size)
{
    const float* x        = (const float*)d_in[0];
    const float* W_ioux_v = (const float*)d_in[2];
    const float* b_ioux_v = (const float*)d_in[3];
    const float* W_iouh_v = (const float*)d_in[4];
    const float* b_iouh_v = (const float*)d_in[5];
    const float* W_fx_v   = (const float*)d_in[6];
    const float* b_fx_v   = (const float*)d_in[7];
    const float* W_fh_v   = (const float*)d_in[8];
    const float* b_fh_v   = (const float*)d_in[9];
    const float* W_ioux_l = (const float*)d_in[10];
    const float* b_ioux_l = (const float*)d_in[11];
    const float* W_iouh_l = (const float*)d_in[12];
    const float* b_iouh_l = (const float*)d_in[13];
    const float* W_fx_l   = (const float*)d_in[14];
    const float* b_fx_l   = (const float*)d_in[15];
    const float* W_fh_l   = (const float*)d_in[16];
    const float* b_fh_l   = (const float*)d_in[17];
    const float* W_type   = (const float*)d_in[18];
    const float* b_type   = (const float*)d_in[19];
    float* h_out = (float*)d_out;

    cudaFuncSetAttribute(gemm_big, cudaFuncAttributeMaxDynamicSharedMemorySize, SMEM_BIG);
    cudaFuncSetAttribute(gemm_lvl, cudaFuncAttributeMaxDynamicSharedMemorySize, SMEM_LVL);

    __nv_bfloat16 *p_xsplit, *p_hsplit, *p_hsumsplit, *p_Wmod, *p_Wiouh, *p_Wfh;
    float *p_bmod, *p_pre, *p_hsiou, *p_fh;
    int *p_gcnt, *p_gidx, *p_lcnt, *p_lidx_v, *p_lidx_l;
    cudaGetSymbolAddress((void**)&p_xsplit,    g_xsplit);
    cudaGetSymbolAddress((void**)&p_hsplit,    g_hsplit);
    cudaGetSymbolAddress((void**)&p_hsumsplit, g_hsumsplit);
    cudaGetSymbolAddress((void**)&p_Wmod,      g_Wmod);
    cudaGetSymbolAddress((void**)&p_Wiouh,     g_Wiouh_m);
    cudaGetSymbolAddress((void**)&p_Wfh,       g_Wfh_m);
    cudaGetSymbolAddress((void**)&p_bmod,      g_bmod);
    cudaGetSymbolAddress((void**)&p_pre,       g_pre);
    cudaGetSymbolAddress((void**)&p_hsiou,     g_hsiou);
    cudaGetSymbolAddress((void**)&p_fh,        g_fh);
    cudaGetSymbolAddress((void**)&p_gcnt,      g_gcnt);
    cudaGetSymbolAddress((void**)&p_gidx,      g_gidx);
    cudaGetSymbolAddress((void**)&p_lcnt,      g_lcnt);
    cudaGetSymbolAddress((void**)&p_lidx_v,    g_lidx_v);
    cudaGetSymbolAddress((void**)&p_lidx_l,    g_lidx_l);

    // counters: zero-initialized at module load; re-zeroed by level-0 gates_kernel
    sel_group<<<(NNODES + 7) / 8, 256>>>(x, W_type, b_type);
    pack_all<<<(PACK_TOTAL + 255) / 256, 256>>>(
        x, W_ioux_v, W_ioux_l, W_fx_v, W_fx_l, W_iouh_v, W_iouh_l, W_fh_v, W_fh_l,
        b_ioux_v, b_ioux_l, b_fx_v, b_fx_l);

    // big precompute GEMM (BN=128)
    {
        GDesc4 dd;
        for (int m = 0; m < 2; m++) {
            for (int lf = 0; lf < 2; lf++) {
                GDesc& d = dd.d[2 * m + lf];
                d.A = p_xsplit;
                d.B = p_Wmod + (size_t)m * 2048 * KPS;
                d.bias = p_bmod + (size_t)m * 2048;
                d.C = p_pre;
                d.cnt = p_gcnt + 2 * m + lf;
                d.idx = p_gidx + (2 * m + lf) * NNODES;
                d.child4 = 0; d.sub = 0; d.csub = 0; d.ldc = 2048;
                d.Nc = lf ? 1536 : 2048;
            }
        }
        gemm_big<<<dim3(2048 / 128, 32, 4), 256, SMEM_BIG>>>(dd);
    }

    leaf_kernel<<<(NLEAF * 256) / 256, 256>>>(b_iouh_v, b_iouh_l, h_out);

    static const int ST[8] = {0, 1, 5, 21, 85, 341, 1365, 5461};
    for (int l = 5; l >= 0; --l) {
        int s  = ST[l];
        int S1 = ST[l + 1];
        int E  = ST[l + 1] - ST[l];
        hsum_kernel<<<(E * 256 + 255) / 256, 256>>>(h_out, S1, E);

        GDesc4 dd;
        for (int m = 0; m < 2; m++) {
            const int* lidx = (m ? p_lidx_l : p_lidx_v) + s;
            const int* lcnt = p_lcnt + 2 * l + m;
            GDesc& di = dd.d[2 * m];
            di.A = p_hsumsplit;
            di.B = p_Wiouh + (size_t)m * 1536 * KPS;
            di.bias = nullptr;
            di.C = p_hsiou;
            di.cnt = lcnt; di.idx = lidx;
            di.child4 = 0; di.sub = s; di.csub = 0; di.ldc = 1536; di.Nc = 1536;
            GDesc& df = dd.d[2 * m + 1];
            df.A = p_hsplit;
            df.B = p_Wfh + (size_t)m * 512 * KPS;
            df.bias = nullptr;
            df.C = p_fh;
            df.cnt = lcnt; df.idx = lidx;
            df.child4 = 1; df.sub = 0; df.csub = S1; df.ldc = 512; df.Nc = 512;
        }
        int ytiles = (4 * E + 127) / 128;
        gemm_lvl<<<dim3(1536 / 64, ytiles, 4), 256, SMEM_LVL>>>(dd);

        gates_kernel<<<(E * 256 + 255) / 256, 256>>>(
            s, S1, E, b_iouh_v, b_iouh_l, b_fh_v, b_fh_l, h_out);
    }
}